// round 12
// baseline (speedup 1.0000x reference)
#include <cuda_runtime.h>
#include <cuda_bf16.h>
#include <cstdint>

#define BS   8192
#define DIM  4096
#define BLK  64
#define NB   64
#define HID  128

// ================= device scratch (no allocs allowed) =================
__device__ float g_bufA[(size_t)BS * DIM];
__device__ float g_bufB[(size_t)BS * DIM];
// prepped bf16 hi/lo weights, dense k-contiguous:
//   W1^T: [t][e=128][d=64]   W2^T: [t][o=64][e=128]     (t = layer*64 + n)
__device__ __nv_bfloat16 g_w1t_hi[2 * 64 * 8192];
__device__ __nv_bfloat16 g_w1t_lo[2 * 64 * 8192];
__device__ __nv_bfloat16 g_w2t_hi[2 * 64 * 8192];
__device__ __nv_bfloat16 g_w2t_lo[2 * 64 * 8192];

// ================= smem layout (bytes) =================
// Phase 1 (GEMM1):   A hi/lo [0,36864)   W1 hi/lo [36864,73728)
// Phase 2 (after bar): partial0 [0,34816)  partial1 [36864,71680)  (overlay A/W1)
// Always:            W2 hi/lo [73728,108544)   b1/b2 [108544,109312)
#define SB_AHI    0
#define SB_ALO    18432
#define SB_W1HI   36864
#define SB_W1LO   55296
#define SB_P0     0
#define SB_P1     36864
#define SB_W2HI   73728
#define SB_W2LO   91136
#define SB_B1     108544
#define SB_B2     109056
#define SMEM_TOTAL 109312

#define LDA 72    // bf16 stride, A / W1^T  (144 B/row: LDSM conflict-free)
#define LDH 136   // bf16 stride, W2^T      (272 B/row: LDSM conflict-free)

__device__ __forceinline__ uint32_t smem_u32(const void* p) {
    uint32_t a;
    asm("{ .reg .u64 t; cvta.to.shared.u64 t, %1; cvt.u32.u64 %0, t; }" : "=r"(a) : "l"(p));
    return a;
}

__device__ __forceinline__ uint32_t pack_bf(float a, float b) {
    uint32_t lo = (uint32_t)__bfloat16_as_ushort(__float2bfloat16(a));
    uint32_t hi = (uint32_t)__bfloat16_as_ushort(__float2bfloat16(b));
    return (hi << 16) | lo;
}

__device__ __forceinline__ void mma16816(float* c, uint32_t a0, uint32_t a1,
                                         uint32_t a2, uint32_t a3,
                                         uint32_t b0, uint32_t b1) {
    asm("mma.sync.aligned.m16n8k16.row.col.f32.bf16.bf16.f32 "
        "{%0,%1,%2,%3}, {%4,%5,%6,%7}, {%8,%9}, {%0,%1,%2,%3};"
        : "+f"(c[0]), "+f"(c[1]), "+f"(c[2]), "+f"(c[3])
        : "r"(a0), "r"(a1), "r"(a2), "r"(a3), "r"(b0), "r"(b1));
}

__device__ __forceinline__ void ldsm4(uint32_t& r0, uint32_t& r1, uint32_t& r2,
                                      uint32_t& r3, uint32_t addr) {
    asm volatile("ldmatrix.sync.aligned.m8n8.x4.shared.b16 {%0,%1,%2,%3}, [%4];"
                 : "=r"(r0), "=r"(r1), "=r"(r2), "=r"(r3) : "r"(addr));
}

__device__ __forceinline__ float elu1(float v) {
    return (v > 0.f) ? v : (__expf(v) - 1.f);
}

// ============== weight prep: fp32 -> transposed bf16 hi/lo ==============
__global__ void prep_weights(const float* __restrict__ w1, const float* __restrict__ w2)
{
    size_t idx = (size_t)blockIdx.x * blockDim.x + threadIdx.x;
    const size_t HALF = (size_t)2 * 64 * 64 * 128;   // 1,048,576
    if (idx < HALF) {
        int e = idx & 127, d = (idx >> 7) & 63;
        size_t t = idx >> 13;
        float v = w1[idx];
        __nv_bfloat16 h = __float2bfloat16(v);
        g_w1t_hi[t * 8192 + e * 64 + d] = h;
        g_w1t_lo[t * 8192 + e * 64 + d] = __float2bfloat16(v - __bfloat162float(h));
    } else if (idx < 2 * HALF) {
        size_t i2 = idx - HALF;
        int o = i2 & 63, e = (i2 >> 6) & 127;
        size_t t = i2 >> 13;
        float v = w2[i2];
        __nv_bfloat16 h = __float2bfloat16(v);
        g_w2t_hi[t * 8192 + o * 128 + e] = h;
        g_w2t_lo[t * 8192 + o * 128 + e] = __float2bfloat16(v - __bfloat162float(h));
    }
}

// ============== fused block MLP: GEMM2 fed from GEMM1 accumulators ==============
__global__ __launch_bounds__(512, 2)
void mlp_tc_kernel(const float* __restrict__ act_in, float* __restrict__ act_out,
                   int layer, const float* __restrict__ b1g, const float* __restrict__ b2g)
{
    extern __shared__ unsigned char smem[];
    float* b1s = (float*)(smem + SB_B1);
    float* b2s = (float*)(smem + SB_B2);
    float* P0  = (float*)(smem + SB_P0);
    float* P1  = (float*)(smem + SB_P1);
    const uint32_t sb = smem_u32(smem);

    const int tid = threadIdx.x;
    const int m = blockIdx.x, n = blockIdx.y;
    const size_t t = (size_t)layer * 64 + n;
    const size_t row0 = (size_t)m * 128;

    // ---- load A tile + convert to bf16 hi/lo inline ----
    {
        const float* src = act_in + row0 * DIM + (size_t)n * BLK;
        for (int idx = tid; idx < 2048; idx += 512) {
            int rr = idx >> 4, c4 = idx & 15;
            float4 v = *reinterpret_cast<const float4*>(src + (size_t)rr * DIM + c4 * 4);
            float h0 = __bfloat162float(__float2bfloat16(v.x));
            float h1 = __bfloat162float(__float2bfloat16(v.y));
            float h2 = __bfloat162float(__float2bfloat16(v.z));
            float h3 = __bfloat162float(__float2bfloat16(v.w));
            uint2 hi, lo;
            hi.x = pack_bf(h0, h1);       hi.y = pack_bf(h2, h3);
            lo.x = pack_bf(v.x - h0, v.y - h1);
            lo.y = pack_bf(v.z - h2, v.w - h3);
            uint32_t off = (uint32_t)(rr * LDA + c4 * 4) * 2;
            *(uint2*)(smem + SB_AHI + off) = hi;
            *(uint2*)(smem + SB_ALO + off) = lo;
        }
    }
    // ---- copy weights into padded smem tiles ----
    {
        const uint32_t* s1h = (const uint32_t*)(g_w1t_hi + t * 8192);
        const uint32_t* s1l = (const uint32_t*)(g_w1t_lo + t * 8192);
        const uint32_t* s2h = (const uint32_t*)(g_w2t_hi + t * 8192);
        const uint32_t* s2l = (const uint32_t*)(g_w2t_lo + t * 8192);
        for (int i = tid; i < 4096; i += 512) {
            int e = i >> 5, p = i & 31;
            uint32_t doff = (uint32_t)(e * LDA + p * 2) * 2;
            *(uint32_t*)(smem + SB_W1HI + doff) = s1h[i];
            *(uint32_t*)(smem + SB_W1LO + doff) = s1l[i];
            int o = i >> 6, q = i & 63;
            uint32_t doff2 = (uint32_t)(o * LDH + q * 2) * 2;
            *(uint32_t*)(smem + SB_W2HI + doff2) = s2h[i];
            *(uint32_t*)(smem + SB_W2LO + doff2) = s2l[i];
        }
        if (tid < 128)      b1s[tid] = b1g[(size_t)n * HID + tid];
        else if (tid < 192) b2s[tid - 128] = b2g[(size_t)n * BLK + (tid - 128)];
    }
    __syncthreads();

    const int w = tid >> 5, lane = tid & 31;
    const int stripe = w >> 1, nh = w & 1;           // 8 row-stripes x 2 N-halves
    const int g = lane >> 2, tg = lane & 3;
    const int row = stripe * 16 + g;

    // ldmatrix address pieces
    const uint32_t arow = (uint32_t)(stripe * 16 + (lane & 15));
    const uint32_t akh  = (uint32_t)((lane >> 4) << 4);           // 0/16 bytes
    const uint32_t baseAhi = sb + SB_AHI + arow * (LDA * 2) + akh;
    const uint32_t baseAlo = sb + SB_ALO + arow * (LDA * 2) + akh;
    const uint32_t bmi  = (uint32_t)(lane >> 3);
    const uint32_t bkh  = (bmi & 1) << 4;
    const uint32_t brow = (uint32_t)(((bmi >> 1) << 3) + (lane & 7));   // 0..15 within tile pair
    const uint32_t baseW1hi = sb + SB_W1HI + ((uint32_t)nh * 64 + brow) * (LDA * 2) + bkh;
    const uint32_t baseW1lo = sb + SB_W1LO + ((uint32_t)nh * 64 + brow) * (LDA * 2) + bkh;

    // ================= GEMM1: H(128x128) = split(A) @ split(W1^T) =================
    float acc[8][4];
#pragma unroll
    for (int i = 0; i < 8; i++) { acc[i][0] = acc[i][1] = acc[i][2] = acc[i][3] = 0.f; }

#pragma unroll
    for (int kt = 0; kt < 4; kt++) {
        const uint32_t ko = (uint32_t)kt * 32;
        uint32_t ah0, ah1, ah2, ah3, al0, al1, al2, al3;
        ldsm4(ah0, ah1, ah2, ah3, baseAhi + ko);
        ldsm4(al0, al1, al2, al3, baseAlo + ko);
#pragma unroll
        for (int p = 0; p < 4; p++) {                 // nt pair (2p, 2p+1)
            uint32_t bh0a, bh1a, bh0b, bh1b, bl0a, bl1a, bl0b, bl1b;
            ldsm4(bh0a, bh1a, bh0b, bh1b, baseW1hi + (uint32_t)p * (16 * LDA * 2) + ko);
            ldsm4(bl0a, bl1a, bl0b, bl1b, baseW1lo + (uint32_t)p * (16 * LDA * 2) + ko);
            mma16816(acc[2 * p],     ah0, ah1, ah2, ah3, bh0a, bh1a);
            mma16816(acc[2 * p],     ah0, ah1, ah2, ah3, bl0a, bl1a);
            mma16816(acc[2 * p],     al0, al1, al2, al3, bh0a, bh1a);
            mma16816(acc[2 * p + 1], ah0, ah1, ah2, ah3, bh0b, bh1b);
            mma16816(acc[2 * p + 1], ah0, ah1, ah2, ah3, bl0b, bl1b);
            mma16816(acc[2 * p + 1], al0, al1, al2, al3, bh0b, bh1b);
        }
    }
    __syncthreads();   // A/W1 smem dead -> partial buffers may overlay

    // ---- in-register epilogue 1: bias + ELU, split -> GEMM2 A-fragments ----
    // acc tile pair (2k2, 2k2+1) becomes the k16 A-fragment for GEMM2 k-step k2.
    uint32_t fh[4][4], fl[4][4];
#pragma unroll
    for (int k2 = 0; k2 < 4; k2++) {
#pragma unroll
        for (int j = 0; j < 2; j++) {
            const int tile = 2 * k2 + j;
            const int c0 = nh * 64 + tile * 8 + 2 * tg;
            float v0 = elu1(acc[tile][0] + b1s[c0]);
            float v1 = elu1(acc[tile][1] + b1s[c0 + 1]);
            float v2 = elu1(acc[tile][2] + b1s[c0]);
            float v3 = elu1(acc[tile][3] + b1s[c0 + 1]);
            float h0 = __bfloat162float(__float2bfloat16(v0));
            float h1 = __bfloat162float(__float2bfloat16(v1));
            float h2 = __bfloat162float(__float2bfloat16(v2));
            float h3 = __bfloat162float(__float2bfloat16(v3));
            fh[k2][2 * j]     = pack_bf(h0, h1);
            fh[k2][2 * j + 1] = pack_bf(h2, h3);
            fl[k2][2 * j]     = pack_bf(v0 - h0, v1 - h1);
            fl[k2][2 * j + 1] = pack_bf(v2 - h2, v3 - h3);
        }
    }

    // ================= GEMM2 (k-split): O_partial[16x64] over e in nh-half =================
    // B fragments: W2^T rows = o, k = e in [nh*64 + k2*16).
    float* Pme = (nh == 0) ? P0 : P1;
#pragma unroll
    for (int half = 0; half < 2; half++) {           // output cols half*32..+31
        float acc2[4][4];
#pragma unroll
        for (int i = 0; i < 4; i++) { acc2[i][0] = acc2[i][1] = acc2[i][2] = acc2[i][3] = 0.f; }
#pragma unroll
        for (int k2 = 0; k2 < 4; k2++) {
            const uint32_t eo = ((uint32_t)nh * 64 + (uint32_t)k2 * 16) * 2;  // bytes along e
#pragma unroll
            for (int p = 0; p < 2; p++) {            // nt pair (2p, 2p+1) within half
                const uint32_t orow = ((uint32_t)half * 32 + (uint32_t)p * 16 + brow);
                uint32_t a2h = sb + SB_W2HI + orow * (LDH * 2) + bkh + eo;
                uint32_t a2l = sb + SB_W2LO + orow * (LDH * 2) + bkh + eo;
                uint32_t bh0a, bh1a, bh0b, bh1b, bl0a, bl1a, bl0b, bl1b;
                ldsm4(bh0a, bh1a, bh0b, bh1b, a2h);
                ldsm4(bl0a, bl1a, bl0b, bl1b, a2l);
                mma16816(acc2[2 * p],     fh[k2][0], fh[k2][1], fh[k2][2], fh[k2][3], bh0a, bh1a);
                mma16816(acc2[2 * p],     fh[k2][0], fh[k2][1], fh[k2][2], fh[k2][3], bl0a, bl1a);
                mma16816(acc2[2 * p],     fl[k2][0], fl[k2][1], fl[k2][2], fl[k2][3], bh0a, bh1a);
                mma16816(acc2[2 * p + 1], fh[k2][0], fh[k2][1], fh[k2][2], fh[k2][3], bh0b, bh1b);
                mma16816(acc2[2 * p + 1], fh[k2][0], fh[k2][1], fh[k2][2], fh[k2][3], bl0b, bl1b);
                mma16816(acc2[2 * p + 1], fl[k2][0], fl[k2][1], fl[k2][2], fl[k2][3], bh0b, bh1b);
            }
        }
        // write k-partial (fragment scatter, 8B stores, conflict-light)
#pragma unroll
        for (int nt = 0; nt < 4; nt++) {
            const int c0 = half * 32 + nt * 8 + 2 * tg;
            float2* q0 = (float2*)&Pme[row * 68 + c0];
            float2* q1 = (float2*)&Pme[(row + 8) * 68 + c0];
            *q0 = make_float2(acc2[nt][0], acc2[nt][1]);
            *q1 = make_float2(acc2[nt][2], acc2[nt][3]);
        }
    }
    __syncthreads();

    // ---- store: p0 + p1 + b2 + residual (gmem), coalesced ----
    {
        const float* rsrc = act_in + row0 * DIM + (size_t)n * BLK;
        float* dst = act_out + row0 * DIM + (size_t)n * BLK;
        for (int idx = tid; idx < 2048; idx += 512) {
            int rr = idx >> 4, c4 = idx & 15;
            float4 p0 = *reinterpret_cast<const float4*>(&P0[rr * 68 + c4 * 4]);
            float4 p1 = *reinterpret_cast<const float4*>(&P1[rr * 68 + c4 * 4]);
            float4 a  = *reinterpret_cast<const float4*>(rsrc + (size_t)rr * DIM + c4 * 4);
            float4 bb = *reinterpret_cast<const float4*>(&b2s[c4 * 4]);
            float4 o;
            o.x = p0.x + p1.x + bb.x + a.x;
            o.y = p0.y + p1.y + bb.y + a.y;
            o.z = p0.z + p1.z + bb.z + a.z;
            o.w = p0.w + p1.w + bb.w + a.w;
            *reinterpret_cast<float4*>(dst + (size_t)rr * DIM + c4 * 4) = o;
        }
    }
}

// ============== per-row 64x64 transpose, 2 rows/CTA, float4 both sides ==============
__global__ __launch_bounds__(256)
void transpose64_kernel(const float* __restrict__ in, float* __restrict__ out)
{
    __shared__ float s[2][64 * 65];
    const size_t base = (size_t)blockIdx.x * 2 * DIM;
    const int tid = threadIdx.x;
    for (int i = tid; i < 2048; i += 256) {
        int r = i >> 10, j = i & 1023;
        int a = j >> 4, q = j & 15;
        float4 v = *reinterpret_cast<const float4*>(in + base + (size_t)r * DIM + a * 64 + q * 4);
        float* sp = &s[r][a * 65 + q * 4];
        sp[0] = v.x; sp[1] = v.y; sp[2] = v.z; sp[3] = v.w;
    }
    __syncthreads();
    for (int i = tid; i < 2048; i += 256) {
        int r = i >> 10, j = i & 1023;
        int b = j >> 4, q = j & 15;
        float4 v;
        v.x = s[r][(q * 4 + 0) * 65 + b];
        v.y = s[r][(q * 4 + 1) * 65 + b];
        v.z = s[r][(q * 4 + 2) * 65 + b];
        v.w = s[r][(q * 4 + 3) * 65 + b];
        *reinterpret_cast<float4*>(out + base + (size_t)r * DIM + b * 64 + q * 4) = v;
    }
}

static float* symbol_addr(const void* sym)
{
    void* p = nullptr;
    cudaGetSymbolAddress(&p, sym);
    return (float*)p;
}

extern "C" void kernel_launch(void* const* d_in, const int* in_sizes, int n_in,
                              void* d_out, int out_size)
{
    (void)in_sizes; (void)n_in; (void)out_size;
    const float* x  = (const float*)d_in[0];
    const float* w1 = (const float*)d_in[1];
    const float* b1 = (const float*)d_in[2];
    const float* w2 = (const float*)d_in[3];
    const float* b2 = (const float*)d_in[4];
    float* out = (float*)d_out;

    float* bufA = symbol_addr(g_bufA);
    float* bufB = symbol_addr(g_bufB);

    cudaFuncSetAttribute((const void*)mlp_tc_kernel,
                         cudaFuncAttributeMaxDynamicSharedMemorySize, SMEM_TOTAL);

    prep_weights<<<4096, 512>>>(w1, w2);

    const dim3 grid(BS / 128, NB);
    const size_t ob1 = (size_t)NB * HID, ob2 = (size_t)NB * BLK;

    // layer 0 (gap=1 shuffle = identity)
    mlp_tc_kernel<<<grid, 512, SMEM_TOTAL>>>(x, bufA, 0, b1, b2);
    // gap=64 shuffle: per-row 64x64 transpose
    transpose64_kernel<<<BS / 2, 256>>>(bufA, bufB);
    // layer 1
    mlp_tc_kernel<<<grid, 512, SMEM_TOTAL>>>(bufB, bufA, 1, b1 + ob1, b2 + ob2);
    // inverse shuffle
    transpose64_kernel<<<BS / 2, 256>>>(bufA, out);
}